// round 1
// baseline (speedup 1.0000x reference)
#include <cuda_runtime.h>
#include <math.h>
#include <stdint.h>

// ---------------------------------------------------------------------------
// graphNet: 4-layer GCN (21->168->84->42->21) + log_softmax
// Strategy:
//   - Precompute deg/dinv and per-edge norm w_e once per launch.
//   - Layer 1: aggregate FIRST (din=21), then GEMM 21->168 (+bias+relu).
//   - Layers 2-4: GEMM first (shrinking dims), then aggregate, +bias+relu.
//   - Final: warp-per-node log_softmax, writes p_z and z.
// Scratch via __device__ globals (no runtime allocation).
// ---------------------------------------------------------------------------

#define N_MAX 100000
#define E_MAX 1600000
#define F_MAX 168

__device__ float g_bufA[(size_t)N_MAX * F_MAX];   // 67.2 MB
__device__ float g_bufB[(size_t)N_MAX * F_MAX];   // 67.2 MB
__device__ float g_w[E_MAX];                      // per-edge norm weight
__device__ float g_dinv[N_MAX];                   // deg -> rsqrt(deg), in place

// ---------------- graph normalization ----------------

__global__ void k_init_deg(float* deg, int n) {
    int i = blockIdx.x * blockDim.x + threadIdx.x;
    if (i < n) deg[i] = 1.0f;   // self-loop contributes 1
}

__global__ void k_count_deg(const int* __restrict__ ei, float* deg, int E) {
    int e = blockIdx.x * blockDim.x + threadIdx.x;
    if (e < E) atomicAdd(&deg[ei[E + e]], 1.0f);   // dst = ei[E+e]
}

__global__ void k_dinv(float* d, int n) {
    int i = blockIdx.x * blockDim.x + threadIdx.x;
    if (i < n) d[i] = rsqrtf(d[i]);   // deg >= 1 always (self-loop)
}

__global__ void k_edge_w(const int* __restrict__ ei, const float* __restrict__ dinv,
                         float* __restrict__ w, int E) {
    int e = blockIdx.x * blockDim.x + threadIdx.x;
    if (e < E) w[e] = dinv[ei[e]] * dinv[ei[E + e]];
}

// ---------------- aggregation ----------------

// out[v] = dinv[v]^2 * h[v]   (self-loop term, also initializes the buffer)
template <int C>
__global__ void k_self_init(const float* __restrict__ h, const float* __restrict__ dinv,
                            float* __restrict__ out, int n) {
    int idx = blockIdx.x * blockDim.x + threadIdx.x;
    if (idx < n * C) {
        int v = idx / C;
        float dv = dinv[v];
        out[idx] = dv * dv * h[idx];
    }
}

// out[dst] += w_e * h[src], thread per (edge, channel)
template <int C>
__global__ void k_edge_agg(const float* __restrict__ h, float* __restrict__ out,
                           const int* __restrict__ ei, const float* __restrict__ w, int E) {
    int idx = blockIdx.x * blockDim.x + threadIdx.x;
    if (idx < E * C) {
        int e = idx / C;
        int c = idx - e * C;
        int s = ei[e];
        int d = ei[E + e];
        atomicAdd(&out[d * C + c], w[e] * h[s * C + c]);
    }
}

template <int C>
__global__ void k_bias_relu(float* __restrict__ x, const float* __restrict__ b, int n) {
    int idx = blockIdx.x * blockDim.x + threadIdx.x;
    if (idx < n * C) {
        int c = idx - (idx / C) * C;
        x[idx] = fmaxf(x[idx] + b[c], 0.0f);
    }
}

// ---------------- GEMM: C[N x M] = A[N x K] @ W[K x M] (+bias, relu) ----------------

#define GBM 64
#define GBN 32
#define GBK 16

__global__ void k_gemm(const float* __restrict__ A, const float* __restrict__ W,
                       const float* __restrict__ bias, float* __restrict__ Cout,
                       int N, int K, int M, int fuse_bias_relu) {
    __shared__ float As[GBK][GBM];
    __shared__ float Bs[GBK][GBN];

    int tid = threadIdx.x;           // 256 threads
    int bm = blockIdx.x * GBM;
    int bn = blockIdx.y * GBN;
    int ty = tid >> 4;               // 0..15
    int tx = tid & 15;               // 0..15
    int row0 = ty * 4;               // 4 rows per thread
    int col0 = tx * 2;               // 2 cols per thread

    float acc[4][2] = {{0.f, 0.f}, {0.f, 0.f}, {0.f, 0.f}, {0.f, 0.f}};

    for (int k0 = 0; k0 < K; k0 += GBK) {
        // load A tile: 64 x 16
#pragma unroll
        for (int i = 0; i < 4; i++) {
            int lin = tid + i * 256;
            int r = lin >> 4;
            int kk = lin & 15;
            int gr = bm + r, gk = k0 + kk;
            As[kk][r] = (gr < N && gk < K) ? A[(size_t)gr * K + gk] : 0.0f;
        }
        // load W tile: 16 x 32
#pragma unroll
        for (int i = 0; i < 2; i++) {
            int lin = tid + i * 256;
            int r = lin >> 5;
            int c = lin & 31;
            int gk = k0 + r, gc = bn + c;
            Bs[r][c] = (gk < K && gc < M) ? W[(size_t)gk * M + gc] : 0.0f;
        }
        __syncthreads();

#pragma unroll
        for (int kk = 0; kk < GBK; kk++) {
            float a0 = As[kk][row0 + 0];
            float a1 = As[kk][row0 + 1];
            float a2 = As[kk][row0 + 2];
            float a3 = As[kk][row0 + 3];
            float b0 = Bs[kk][col0 + 0];
            float b1 = Bs[kk][col0 + 1];
            acc[0][0] += a0 * b0;  acc[0][1] += a0 * b1;
            acc[1][0] += a1 * b0;  acc[1][1] += a1 * b1;
            acc[2][0] += a2 * b0;  acc[2][1] += a2 * b1;
            acc[3][0] += a3 * b0;  acc[3][1] += a3 * b1;
        }
        __syncthreads();
    }

#pragma unroll
    for (int i = 0; i < 4; i++) {
#pragma unroll
        for (int j = 0; j < 2; j++) {
            int gr = bm + row0 + i;
            int gc = bn + col0 + j;
            if (gr < N && gc < M) {
                float v = acc[i][j];
                if (fuse_bias_relu) v = fmaxf(v + bias[gc], 0.0f);
                Cout[(size_t)gr * M + gc] = v;
            }
        }
    }
}

// ---------------- final: bias + relu + log_softmax (warp per node) ----------------

__global__ void k_final(float* __restrict__ zbuf,     // in: raw agg; out: z = relu(agg+b)
                        const float* __restrict__ b,
                        float* __restrict__ pz,       // out: log_softmax(z)
                        int n) {
    int gtid = blockIdx.x * blockDim.x + threadIdx.x;
    int node = gtid >> 5;
    int lane = gtid & 31;
    if (node >= n) return;

    float v = -INFINITY;
    if (lane < 21) v = fmaxf(zbuf[node * 21 + lane] + b[lane], 0.0f);

    float m = v;
#pragma unroll
    for (int o = 16; o > 0; o >>= 1) m = fmaxf(m, __shfl_xor_sync(0xffffffffu, m, o));

    float ex = (lane < 21) ? __expf(v - m) : 0.0f;
    float s = ex;
#pragma unroll
    for (int o = 16; o > 0; o >>= 1) s += __shfl_xor_sync(0xffffffffu, s, o);

    if (lane < 21) {
        zbuf[node * 21 + lane] = v;
        pz[node * 21 + lane] = v - m - __logf(s);
    }
}

// ---------------------------------------------------------------------------

static inline int cdiv(long long a, int b) { return (int)((a + b - 1) / b); }

extern "C" void kernel_launch(void* const* d_in, const int* in_sizes, int n_in,
                              void* d_out, int out_size) {
    const float* x  = (const float*)d_in[0];
    const int*   ei = (const int*)d_in[1];
    const float* W1 = (const float*)d_in[2];  const float* b1 = (const float*)d_in[3];
    const float* W2 = (const float*)d_in[4];  const float* b2 = (const float*)d_in[5];
    const float* W3 = (const float*)d_in[6];  const float* b3 = (const float*)d_in[7];
    const float* W4 = (const float*)d_in[8];  const float* b4 = (const float*)d_in[9];

    const int n = in_sizes[0] / 21;
    const int E = in_sizes[1] / 2;

    float *bufA, *bufB, *w, *dinv;
    cudaGetSymbolAddress((void**)&bufA, g_bufA);
    cudaGetSymbolAddress((void**)&bufB, g_bufB);
    cudaGetSymbolAddress((void**)&w,    g_w);
    cudaGetSymbolAddress((void**)&dinv, g_dinv);

    float* out_pz = (float*)d_out;
    float* out_z  = (float*)d_out + (size_t)n * 21;

    const int T = 256;

    // --- graph normalization ---
    k_init_deg<<<cdiv(n, T), T>>>(dinv, n);
    k_count_deg<<<cdiv(E, T), T>>>(ei, dinv, E);
    k_dinv<<<cdiv(n, T), T>>>(dinv, n);
    k_edge_w<<<cdiv(E, T), T>>>(ei, dinv, w, E);

    // --- layer 1: aggregate (C=21) first, then GEMM 21->168 (+bias+relu) ---
    k_self_init<21><<<cdiv((long long)n * 21, T), T>>>(x, dinv, bufA, n);
    k_edge_agg<21><<<cdiv((long long)E * 21, T), T>>>(x, bufA, ei, w, E);
    {
        dim3 grid(cdiv(n, GBM), cdiv(168, GBN));
        k_gemm<<<grid, T>>>(bufA, W1, b1, bufB, n, 21, 168, 1);   // z1 in bufB [n,168]
    }

    // --- layer 2: GEMM 168->84, then aggregate (C=84), +bias+relu ---
    {
        dim3 grid(cdiv(n, GBM), cdiv(84, GBN));
        k_gemm<<<grid, T>>>(bufB, W2, nullptr, bufA, n, 168, 84, 0);  // t2 in bufA
    }
    k_self_init<84><<<cdiv((long long)n * 84, T), T>>>(bufA, dinv, bufB, n);
    k_edge_agg<84><<<cdiv((long long)E * 84, T), T>>>(bufA, bufB, ei, w, E);
    k_bias_relu<84><<<cdiv((long long)n * 84, T), T>>>(bufB, b2, n);   // z2 in bufB

    // --- layer 3: GEMM 84->42, aggregate (C=42), +bias+relu ---
    {
        dim3 grid(cdiv(n, GBM), cdiv(42, GBN));
        k_gemm<<<grid, T>>>(bufB, W3, nullptr, bufA, n, 84, 42, 0);   // t3 in bufA
    }
    k_self_init<42><<<cdiv((long long)n * 42, T), T>>>(bufA, dinv, bufB, n);
    k_edge_agg<42><<<cdiv((long long)E * 42, T), T>>>(bufA, bufB, ei, w, E);
    k_bias_relu<42><<<cdiv((long long)n * 42, T), T>>>(bufB, b3, n);   // z3 in bufB

    // --- layer 4: GEMM 42->21, aggregate (C=21) into z-region of d_out ---
    {
        dim3 grid(cdiv(n, GBM), cdiv(21, GBN));
        k_gemm<<<grid, T>>>(bufB, W4, nullptr, bufA, n, 42, 21, 0);   // t4 in bufA
    }
    k_self_init<21><<<cdiv((long long)n * 21, T), T>>>(bufA, dinv, out_z, n);
    k_edge_agg<21><<<cdiv((long long)E * 21, T), T>>>(bufA, out_z, ei, w, E);

    // --- final: bias + relu + log_softmax ---
    k_final<<<cdiv((long long)n * 32, T), T>>>(out_z, b4, out_pz, n);
}

// round 2
// speedup vs baseline: 1.8289x; 1.8289x over previous
#include <cuda_runtime.h>
#include <math.h>
#include <stdint.h>

// ---------------------------------------------------------------------------
// graphNet: 4-layer GCN (21->168->84->42->21) + log_softmax.
// Round-2 strategy: CSR-by-dst gather aggregation (no atomics in hot path),
// fused self-loop + bias + relu epilogues, warp-per-node vectorized gathers.
// ---------------------------------------------------------------------------

#define N_MAX 100000
#define E_MAX 1600000
#define F_MAX 168
#define SCAN_B 1024

__device__ float g_bufA[(size_t)N_MAX * F_MAX];   // 67.2 MB
__device__ float g_bufB[(size_t)N_MAX * F_MAX];   // 67.2 MB
__device__ int   g_ideg[N_MAX];                   // in-degree (no self-loop)
__device__ float g_dinv[N_MAX];
__device__ int   g_rowptr[N_MAX + 1];
__device__ int   g_scan_tmp[N_MAX];               // per-elem inclusive scan
__device__ int   g_bsum[256];                     // block sums
__device__ int   g_cur[N_MAX];                    // scatter cursors
__device__ int   g_csr_src[E_MAX];
__device__ float g_csr_w[E_MAX];

// ---------------- degree / dinv ----------------

__global__ void k_count_deg(const int* __restrict__ ei, int* __restrict__ ideg, int E) {
    int e = blockIdx.x * blockDim.x + threadIdx.x;
    if (e < E) atomicAdd(&ideg[ei[E + e]], 1);
}

__global__ void k_dinv(const int* __restrict__ ideg, float* __restrict__ dinv, int n) {
    int i = blockIdx.x * blockDim.x + threadIdx.x;
    if (i < n) dinv[i] = rsqrtf((float)(ideg[i] + 1));   // +1 self-loop
}

// ---------------- block scan (row_ptr) ----------------

__global__ void k_scan_block(const int* __restrict__ in, int* __restrict__ out,
                             int* __restrict__ bsum, int n) {
    __shared__ int s[SCAN_B];
    int i = blockIdx.x * SCAN_B + threadIdx.x;
    s[threadIdx.x] = (i < n) ? in[i] : 0;
    __syncthreads();
#pragma unroll
    for (int off = 1; off < SCAN_B; off <<= 1) {
        int t = (threadIdx.x >= off) ? s[threadIdx.x - off] : 0;
        __syncthreads();
        s[threadIdx.x] += t;
        __syncthreads();
    }
    if (i < n) out[i] = s[threadIdx.x];
    if (bsum && threadIdx.x == SCAN_B - 1) bsum[blockIdx.x] = s[SCAN_B - 1];
}

__global__ void k_add_off(const int* __restrict__ scanned, const int* __restrict__ bscan,
                          int* __restrict__ row_ptr, int n) {
    int i = blockIdx.x * SCAN_B + threadIdx.x;
    if (i < n) {
        int add = blockIdx.x ? bscan[blockIdx.x - 1] : 0;
        row_ptr[i + 1] = scanned[i] + add;
        if (i == 0) row_ptr[0] = 0;
    }
}

// ---------------- CSR scatter ----------------

__global__ void k_scatter(const int* __restrict__ ei, const int* __restrict__ row_ptr,
                          int* __restrict__ cur, const float* __restrict__ dinv,
                          int* __restrict__ csr_src, float* __restrict__ csr_w, int E) {
    int e = blockIdx.x * blockDim.x + threadIdx.x;
    if (e < E) {
        int s = ei[e];
        int d = ei[E + e];
        int pos = atomicAdd(&cur[d], 1);
        int j = row_ptr[d] + pos;
        csr_src[j] = s;
        csr_w[j] = dinv[s] * dinv[d];
    }
}

// ---------------- fused CSR aggregation ----------------
// out[v] = [relu](  dinv[v]^2*h[v] + sum_j w_j*h[src_j]  [+ bias] )
// warp per node; L = C/VW lanes active, each owning VW contiguous channels.

template <int C, int VW>
__global__ void k_agg(const float* __restrict__ h,
                      const int* __restrict__ row_ptr,
                      const int* __restrict__ csr_src,
                      const float* __restrict__ csr_w,
                      const float* __restrict__ dinv,
                      const float* __restrict__ bias,   // null -> raw agg
                      float* __restrict__ out, int n) {
    constexpr int L = C / VW;                 // 21 for all our configs
    int v = (blockIdx.x * blockDim.x + threadIdx.x) >> 5;
    int lane = threadIdx.x & 31;
    if (v >= n || lane >= L) return;

    int beg = row_ptr[v], end = row_ptr[v + 1];
    float acc[VW];
#pragma unroll
    for (int k = 0; k < VW; k++) acc[k] = 0.0f;

    const float* __restrict__ hb = h;
    int j = beg;
    for (; j + 2 <= end; j += 2) {
        int   s0 = csr_src[j],   s1 = csr_src[j + 1];
        float w0 = csr_w[j],     w1 = csr_w[j + 1];
        const float* p0 = hb + (size_t)s0 * C + lane * VW;
        const float* p1 = hb + (size_t)s1 * C + lane * VW;
        float f0[VW], f1[VW];
#pragma unroll
        for (int k = 0; k < VW; k++) { f0[k] = p0[k]; f1[k] = p1[k]; }
#pragma unroll
        for (int k = 0; k < VW; k++) acc[k] += w0 * f0[k] + w1 * f1[k];
    }
    if (j < end) {
        int s0 = csr_src[j];
        float w0 = csr_w[j];
        const float* p0 = hb + (size_t)s0 * C + lane * VW;
#pragma unroll
        for (int k = 0; k < VW; k++) acc[k] += w0 * p0[k];
    }

    float dv = dinv[v];
    float dv2 = dv * dv;
    const float* pv = hb + (size_t)v * C + lane * VW;
    float* po = out + (size_t)v * C + lane * VW;
#pragma unroll
    for (int k = 0; k < VW; k++) {
        float r = acc[k] + dv2 * pv[k];
        if (bias) r = fmaxf(r + bias[lane * VW + k], 0.0f);
        po[k] = r;
    }
}

// ---------------- GEMM: C[N x M] = A[N x K] @ W[K x M] (+bias, relu) ----------------

#define GBM 64
#define GBN 32
#define GBK 16

__global__ void k_gemm(const float* __restrict__ A, const float* __restrict__ W,
                       const float* __restrict__ bias, float* __restrict__ Cout,
                       int N, int K, int M, int fuse_bias_relu) {
    __shared__ float As[GBK][GBM];
    __shared__ float Bs[GBK][GBN];

    int tid = threadIdx.x;           // 256 threads
    int bm = blockIdx.x * GBM;
    int bn = blockIdx.y * GBN;
    int ty = tid >> 4;
    int tx = tid & 15;
    int row0 = ty * 4;
    int col0 = tx * 2;

    float acc[4][2] = {{0.f, 0.f}, {0.f, 0.f}, {0.f, 0.f}, {0.f, 0.f}};

    for (int k0 = 0; k0 < K; k0 += GBK) {
#pragma unroll
        for (int i = 0; i < 4; i++) {
            int lin = tid + i * 256;
            int r = lin >> 4;
            int kk = lin & 15;
            int gr = bm + r, gk = k0 + kk;
            As[kk][r] = (gr < N && gk < K) ? A[(size_t)gr * K + gk] : 0.0f;
        }
#pragma unroll
        for (int i = 0; i < 2; i++) {
            int lin = tid + i * 256;
            int r = lin >> 5;
            int c = lin & 31;
            int gk = k0 + r, gc = bn + c;
            Bs[r][c] = (gk < K && gc < M) ? W[(size_t)gk * M + gc] : 0.0f;
        }
        __syncthreads();

#pragma unroll
        for (int kk = 0; kk < GBK; kk++) {
            float a0 = As[kk][row0 + 0];
            float a1 = As[kk][row0 + 1];
            float a2 = As[kk][row0 + 2];
            float a3 = As[kk][row0 + 3];
            float b0 = Bs[kk][col0 + 0];
            float b1 = Bs[kk][col0 + 1];
            acc[0][0] += a0 * b0;  acc[0][1] += a0 * b1;
            acc[1][0] += a1 * b0;  acc[1][1] += a1 * b1;
            acc[2][0] += a2 * b0;  acc[2][1] += a2 * b1;
            acc[3][0] += a3 * b0;  acc[3][1] += a3 * b1;
        }
        __syncthreads();
    }

#pragma unroll
    for (int i = 0; i < 4; i++) {
#pragma unroll
        for (int j = 0; j < 2; j++) {
            int gr = bm + row0 + i;
            int gc = bn + col0 + j;
            if (gr < N && gc < M) {
                float v = acc[i][j];
                if (fuse_bias_relu) v = fmaxf(v + bias[gc], 0.0f);
                Cout[(size_t)gr * M + gc] = v;
            }
        }
    }
}

// ---------------- final: CSR agg + bias + relu + log_softmax ----------------
// t4 = h3 @ W4 (raw). Computes z = relu(agg(t4)+b4), p_z = log_softmax(z).

__global__ void k_final(const float* __restrict__ t4,
                        const int* __restrict__ row_ptr,
                        const int* __restrict__ csr_src,
                        const float* __restrict__ csr_w,
                        const float* __restrict__ dinv,
                        const float* __restrict__ b4,
                        float* __restrict__ out_z, float* __restrict__ out_pz, int n) {
    int v = (blockIdx.x * blockDim.x + threadIdx.x) >> 5;
    int lane = threadIdx.x & 31;
    if (v >= n) return;

    float val = -INFINITY;
    if (lane < 21) {
        float acc = 0.0f;
        int beg = row_ptr[v], end = row_ptr[v + 1];
        int j = beg;
        for (; j + 2 <= end; j += 2) {
            int   s0 = csr_src[j],   s1 = csr_src[j + 1];
            float w0 = csr_w[j],     w1 = csr_w[j + 1];
            float f0 = t4[(size_t)s0 * 21 + lane];
            float f1 = t4[(size_t)s1 * 21 + lane];
            acc += w0 * f0 + w1 * f1;
        }
        if (j < end) acc += csr_w[j] * t4[(size_t)csr_src[j] * 21 + lane];
        float dv = dinv[v];
        acc += dv * dv * t4[(size_t)v * 21 + lane];
        val = fmaxf(acc + b4[lane], 0.0f);
    }

    float m = val;
#pragma unroll
    for (int o = 16; o > 0; o >>= 1) m = fmaxf(m, __shfl_xor_sync(0xffffffffu, m, o));

    float ex = (lane < 21) ? __expf(val - m) : 0.0f;
    float s = ex;
#pragma unroll
    for (int o = 16; o > 0; o >>= 1) s += __shfl_xor_sync(0xffffffffu, s, o);

    if (lane < 21) {
        out_z[(size_t)v * 21 + lane] = val;
        out_pz[(size_t)v * 21 + lane] = val - m - __logf(s);
    }
}

// ---------------------------------------------------------------------------

static inline int cdiv(long long a, int b) { return (int)((a + b - 1) / b); }

extern "C" void kernel_launch(void* const* d_in, const int* in_sizes, int n_in,
                              void* d_out, int out_size) {
    const float* x  = (const float*)d_in[0];
    const int*   ei = (const int*)d_in[1];
    const float* W1 = (const float*)d_in[2];  const float* b1 = (const float*)d_in[3];
    const float* W2 = (const float*)d_in[4];  const float* b2 = (const float*)d_in[5];
    const float* W3 = (const float*)d_in[6];  const float* b3 = (const float*)d_in[7];
    const float* W4 = (const float*)d_in[8];  const float* b4 = (const float*)d_in[9];

    const int n = in_sizes[0] / 21;
    const int E = in_sizes[1] / 2;

    float *bufA, *bufB, *dinv, *csr_w;
    int *ideg, *row_ptr, *scan_tmp, *bsum, *cur, *csr_src;
    cudaGetSymbolAddress((void**)&bufA, g_bufA);
    cudaGetSymbolAddress((void**)&bufB, g_bufB);
    cudaGetSymbolAddress((void**)&dinv, g_dinv);
    cudaGetSymbolAddress((void**)&ideg, g_ideg);
    cudaGetSymbolAddress((void**)&row_ptr, g_rowptr);
    cudaGetSymbolAddress((void**)&scan_tmp, g_scan_tmp);
    cudaGetSymbolAddress((void**)&bsum, g_bsum);
    cudaGetSymbolAddress((void**)&cur, g_cur);
    cudaGetSymbolAddress((void**)&csr_src, g_csr_src);
    cudaGetSymbolAddress((void**)&csr_w, g_csr_w);

    float* out_pz = (float*)d_out;
    float* out_z  = (float*)d_out + (size_t)n * 21;

    const int T = 256;
    const int nb = cdiv(n, SCAN_B);

    // --- CSR build + normalization ---
    cudaMemsetAsync(ideg, 0, (size_t)n * sizeof(int));
    k_count_deg<<<cdiv(E, T), T>>>(ei, ideg, E);
    k_dinv<<<cdiv(n, T), T>>>(ideg, dinv, n);
    k_scan_block<<<nb, SCAN_B>>>(ideg, scan_tmp, bsum, n);
    k_scan_block<<<1, SCAN_B>>>(bsum, bsum, nullptr, nb);
    k_add_off<<<nb, SCAN_B>>>(scan_tmp, bsum, row_ptr, n);
    cudaMemsetAsync(cur, 0, (size_t)n * sizeof(int));
    k_scatter<<<cdiv(E, T), T>>>(ei, row_ptr, cur, dinv, csr_src, csr_w, E);

    const int aggGrid = cdiv((long long)n * 32, T);

    // --- layer 1: aggregate x (C=21) first, then GEMM 21->168 (+bias+relu) ---
    k_agg<21, 1><<<aggGrid, T>>>(x, row_ptr, csr_src, csr_w, dinv, nullptr, bufA, n);
    {
        dim3 grid(cdiv(n, GBM), cdiv(168, GBN));
        k_gemm<<<grid, T>>>(bufA, W1, b1, bufB, n, 21, 168, 1);       // h1 in bufB
    }

    // --- layer 2: GEMM 168->84, then fused agg+bias+relu (C=84, float4) ---
    {
        dim3 grid(cdiv(n, GBM), cdiv(84, GBN));
        k_gemm<<<grid, T>>>(bufB, W2, nullptr, bufA, n, 168, 84, 0);  // t2 in bufA
    }
    k_agg<84, 4><<<aggGrid, T>>>(bufA, row_ptr, csr_src, csr_w, dinv, b2, bufB, n);

    // --- layer 3: GEMM 84->42, fused agg+bias+relu (C=42, float2) ---
    {
        dim3 grid(cdiv(n, GBM), cdiv(42, GBN));
        k_gemm<<<grid, T>>>(bufB, W3, nullptr, bufA, n, 84, 42, 0);   // t3 in bufA
    }
    k_agg<42, 2><<<aggGrid, T>>>(bufA, row_ptr, csr_src, csr_w, dinv, b3, bufB, n);

    // --- layer 4: GEMM 42->21, then fused agg+bias+relu+log_softmax ---
    {
        dim3 grid(cdiv(n, GBM), cdiv(21, GBN));
        k_gemm<<<grid, T>>>(bufB, W4, nullptr, bufA, n, 42, 21, 0);   // t4 in bufA
    }
    k_final<<<aggGrid, T>>>(bufA, row_ptr, csr_src, csr_w, dinv, b4, out_z, out_pz, n);
}

// round 3
// speedup vs baseline: 2.7531x; 1.5053x over previous
#include <cuda_runtime.h>
#include <math.h>
#include <stdint.h>

// ---------------------------------------------------------------------------
// graphNet: 4-layer GCN (21->168->84->42->21) + log_softmax.
// Round-3: padded CSR (deg rounded to 4) with interleaved {src,w} records,
// 8-deep gather bursts; 8x4-microtile FMA-bound SGEMM with padded strides.
// ---------------------------------------------------------------------------

#define N_MAX 100000
#define E_MAX 1600000
#define F_MAX 168
#define CSR_MAX (E_MAX + 4 * N_MAX)
#define SCAN_B 1024

struct __align__(8) Edge { int src; float w; };

__device__ float g_bufA[(size_t)N_MAX * F_MAX];
__device__ float g_bufB[(size_t)N_MAX * F_MAX];
__device__ int   g_ideg[N_MAX];
__device__ float g_dinv[N_MAX];
__device__ int   g_rowptr[N_MAX + 1];
__device__ int   g_scan_tmp[N_MAX];
__device__ int   g_bsum[256];
__device__ int   g_cur[N_MAX];
__device__ Edge  g_csr[CSR_MAX];

// ---------------- degree ----------------

__global__ void k_count_deg(const int* __restrict__ ei, int* __restrict__ ideg, int E) {
    int e = blockIdx.x * blockDim.x + threadIdx.x;
    if (e < E) atomicAdd(&ideg[ei[E + e]], 1);
}

// ---------------- block scan over padded degrees ----------------

__global__ void k_scan_block(const int* __restrict__ in, int* __restrict__ out,
                             int* __restrict__ bsum, int n, int pad) {
    __shared__ int s[SCAN_B];
    int i = blockIdx.x * SCAN_B + threadIdx.x;
    int val = (i < n) ? in[i] : 0;
    if (pad) val = (val + 3) & ~3;         // round deg up to multiple of 4
    s[threadIdx.x] = val;
    __syncthreads();
#pragma unroll
    for (int off = 1; off < SCAN_B; off <<= 1) {
        int t = (threadIdx.x >= off) ? s[threadIdx.x - off] : 0;
        __syncthreads();
        s[threadIdx.x] += t;
        __syncthreads();
    }
    if (i < n) out[i] = s[threadIdx.x];
    if (bsum && threadIdx.x == SCAN_B - 1) bsum[blockIdx.x] = s[SCAN_B - 1];
}

// row_ptr from scan, plus dinv (fused)
__global__ void k_add_off(const int* __restrict__ scanned, const int* __restrict__ bscan,
                          const int* __restrict__ ideg,
                          int* __restrict__ row_ptr, float* __restrict__ dinv, int n) {
    int i = blockIdx.x * SCAN_B + threadIdx.x;
    if (i < n) {
        int add = blockIdx.x ? bscan[blockIdx.x - 1] : 0;
        row_ptr[i + 1] = scanned[i] + add;
        if (i == 0) row_ptr[0] = 0;
        dinv[i] = rsqrtf((float)(ideg[i] + 1));
    }
}

// ---------------- CSR scatter ----------------

__global__ void k_scatter(const int* __restrict__ ei, const int* __restrict__ row_ptr,
                          int* __restrict__ cur, const float* __restrict__ dinv,
                          Edge* __restrict__ csr, int E) {
    int e = blockIdx.x * blockDim.x + threadIdx.x;
    if (e < E) {
        int s = ei[e];
        int d = ei[E + e];
        int pos = atomicAdd(&cur[d], 1);
        int j = row_ptr[d] + pos;
        float2 rec = make_float2(__int_as_float(s), dinv[s] * dinv[d]);
        *reinterpret_cast<float2*>(&csr[j]) = rec;
    }
}

// ---------------- vector row load helper ----------------

template <int VW>
__device__ __forceinline__ void ldrow(float (&f)[VW], const float* __restrict__ p) {
    if (VW == 4) { float4 t = *(const float4*)p; f[0]=t.x; f[1]=t.y; f[2]=t.z; f[3]=t.w; }
    else if (VW == 2) { float2 t = *(const float2*)p; f[0]=t.x; f[1]=t.y; }
    else { f[0] = *p; }
}

// ---------------- fused CSR aggregation ----------------
// out[v] = [relu]( dinv[v]^2*h[v] + sum_j w_j*h[src_j] [+bias] )
// warp per node, L=C/VW lanes active, padded-degree loop (no tail branches).

template <int C, int VW, int SIN, int SOUT>
__global__ void k_agg(const float* __restrict__ h, const int* __restrict__ row_ptr,
                      const Edge* __restrict__ csr, const float* __restrict__ dinv,
                      const float* __restrict__ bias, float* __restrict__ out, int n) {
    constexpr int L = C / VW;
    int v = (blockIdx.x * blockDim.x + threadIdx.x) >> 5;
    int lane = threadIdx.x & 31;
    if (v >= n) return;

    if (lane < L) {
        int beg = row_ptr[v], endp = row_ptr[v + 1];
        const int off = lane * VW;
        float acc[VW];
#pragma unroll
        for (int k = 0; k < VW; k++) acc[k] = 0.f;

        int j = beg;
        for (; j + 8 <= endp; j += 8) {
            int4 e0 = *(const int4*)(csr + j);
            int4 e1 = *(const int4*)(csr + j + 2);
            int4 e2 = *(const int4*)(csr + j + 4);
            int4 e3 = *(const int4*)(csr + j + 6);
            float f[8][VW];
            ldrow<VW>(f[0], h + (size_t)e0.x * SIN + off);
            ldrow<VW>(f[1], h + (size_t)e0.z * SIN + off);
            ldrow<VW>(f[2], h + (size_t)e1.x * SIN + off);
            ldrow<VW>(f[3], h + (size_t)e1.z * SIN + off);
            ldrow<VW>(f[4], h + (size_t)e2.x * SIN + off);
            ldrow<VW>(f[5], h + (size_t)e2.z * SIN + off);
            ldrow<VW>(f[6], h + (size_t)e3.x * SIN + off);
            ldrow<VW>(f[7], h + (size_t)e3.z * SIN + off);
            float w[8];
            w[0] = __int_as_float(e0.y); w[1] = __int_as_float(e0.w);
            w[2] = __int_as_float(e1.y); w[3] = __int_as_float(e1.w);
            w[4] = __int_as_float(e2.y); w[5] = __int_as_float(e2.w);
            w[6] = __int_as_float(e3.y); w[7] = __int_as_float(e3.w);
#pragma unroll
            for (int i = 0; i < 8; i++)
#pragma unroll
                for (int k = 0; k < VW; k++) acc[k] = fmaf(w[i], f[i][k], acc[k]);
        }
        if (j < endp) {   // exactly 4 remain (padded deg % 4 == 0)
            int4 e0 = *(const int4*)(csr + j);
            int4 e1 = *(const int4*)(csr + j + 2);
            float f[4][VW];
            ldrow<VW>(f[0], h + (size_t)e0.x * SIN + off);
            ldrow<VW>(f[1], h + (size_t)e0.z * SIN + off);
            ldrow<VW>(f[2], h + (size_t)e1.x * SIN + off);
            ldrow<VW>(f[3], h + (size_t)e1.z * SIN + off);
            float w[4];
            w[0] = __int_as_float(e0.y); w[1] = __int_as_float(e0.w);
            w[2] = __int_as_float(e1.y); w[3] = __int_as_float(e1.w);
#pragma unroll
            for (int i = 0; i < 4; i++)
#pragma unroll
                for (int k = 0; k < VW; k++) acc[k] = fmaf(w[i], f[i][k], acc[k]);
        }

        float dv = dinv[v];
        float s2 = dv * dv;
        float pvv[VW];
        ldrow<VW>(pvv, h + (size_t)v * SIN + off);
        float* po = out + (size_t)v * SOUT + off;
#pragma unroll
        for (int k = 0; k < VW; k++) {
            float r = fmaf(s2, pvv[k], acc[k]);
            if (bias) r = fmaxf(r + bias[off + k], 0.f);
            po[k] = r;
        }
    } else if (lane * VW < SOUT) {
        // zero the pad columns (needed for downstream float4 GEMM loads)
        float* po = out + (size_t)v * SOUT + lane * VW;
#pragma unroll
        for (int k = 0; k < VW; k++) po[k] = 0.f;
    }
}

// ---------------- GEMM: C[N x M] = A[N x K] @ W[K x M] (+bias, relu) ----------------
// 256x32 block tile, 8x4 microtile, 256 threads. A has padded stride SA (%4==0).

#define GBM 256
#define GBN 32
#define GBK 16

__global__ void __launch_bounds__(256)
k_gemm(const float* __restrict__ A, const float* __restrict__ W,
       const float* __restrict__ bias, float* __restrict__ Cout,
       int N, int K, int M, int SA, int SC, int fuse_bias_relu) {
    __shared__ float As[GBK][GBM];
    __shared__ float Bs[GBK][GBN];

    int tid = threadIdx.x;
    int bm = blockIdx.x * GBM;
    int bn = blockIdx.y * GBN;
    int ty = tid >> 3;                 // 0..31
    int tx = tid & 7;                  // 0..7
    int row0 = ty * 8;
    int col0 = tx * 4;

    float acc[8][4];
#pragma unroll
    for (int i = 0; i < 8; i++)
#pragma unroll
        for (int j = 0; j < 4; j++) acc[i][j] = 0.f;

    for (int k0 = 0; k0 < K; k0 += GBK) {
        // A tile: 256 rows x 16 k, via float4-along-k (4 per thread)
#pragma unroll
        for (int i = 0; i < 4; i++) {
            int lin4 = tid + i * 256;          // 0..1023
            int r = lin4 >> 2;                 // 0..255
            int kk4 = lin4 & 3;                // which float4 group
            int gr = bm + r;
            int gk0 = k0 + kk4 * 4;
            float4 a = make_float4(0.f, 0.f, 0.f, 0.f);
            if (gr < N && gk0 + 3 < SA)
                a = *(const float4*)(A + (size_t)gr * SA + gk0);
            As[kk4 * 4 + 0][r] = a.x;
            As[kk4 * 4 + 1][r] = a.y;
            As[kk4 * 4 + 2][r] = a.z;
            As[kk4 * 4 + 3][r] = a.w;
        }
        // B tile: 16 x 32 (2 per thread)
#pragma unroll
        for (int i = 0; i < 2; i++) {
            int lin = tid + i * 256;
            int r = lin >> 5;
            int c = lin & 31;
            int gk = k0 + r, gc = bn + c;
            Bs[r][c] = (gk < K && gc < M) ? W[(size_t)gk * M + gc] : 0.f;
        }
        __syncthreads();

#pragma unroll
        for (int kk = 0; kk < GBK; kk++) {
            float4 a0 = *(const float4*)&As[kk][row0];
            float4 a1 = *(const float4*)&As[kk][row0 + 4];
            float4 b  = *(const float4*)&Bs[kk][col0];
            float av[8] = {a0.x, a0.y, a0.z, a0.w, a1.x, a1.y, a1.z, a1.w};
            float bv[4] = {b.x, b.y, b.z, b.w};
#pragma unroll
            for (int i = 0; i < 8; i++)
#pragma unroll
                for (int j = 0; j < 4; j++) acc[i][j] = fmaf(av[i], bv[j], acc[i][j]);
        }
        __syncthreads();
    }

#pragma unroll
    for (int i = 0; i < 8; i++) {
        int gr = bm + row0 + i;
        if (gr < N) {
#pragma unroll
            for (int j = 0; j < 4; j++) {
                int gc = bn + col0 + j;
                if (gc < M) {
                    float v = acc[i][j];
                    if (fuse_bias_relu) v = fmaxf(v + bias[gc], 0.f);
                    Cout[(size_t)gr * SC + gc] = v;
                }
            }
        }
    }
}

// ---------------- final: CSR agg + bias + relu + log_softmax ----------------

__global__ void k_final(const float* __restrict__ t4,       // stride 24
                        const int* __restrict__ row_ptr,
                        const Edge* __restrict__ csr,
                        const float* __restrict__ dinv,
                        const float* __restrict__ b4,
                        float* __restrict__ out_z, float* __restrict__ out_pz, int n) {
    int v = (blockIdx.x * blockDim.x + threadIdx.x) >> 5;
    int lane = threadIdx.x & 31;
    if (v >= n) return;

    float val = -INFINITY;
    if (lane < 21) {
        int beg = row_ptr[v], endp = row_ptr[v + 1];
        float acc = 0.f;
        int j = beg;
        for (; j + 8 <= endp; j += 8) {
            int4 e0 = *(const int4*)(csr + j);
            int4 e1 = *(const int4*)(csr + j + 2);
            int4 e2 = *(const int4*)(csr + j + 4);
            int4 e3 = *(const int4*)(csr + j + 6);
            float f0 = t4[(size_t)e0.x * 24 + lane];
            float f1 = t4[(size_t)e0.z * 24 + lane];
            float f2 = t4[(size_t)e1.x * 24 + lane];
            float f3 = t4[(size_t)e1.z * 24 + lane];
            float f4 = t4[(size_t)e2.x * 24 + lane];
            float f5 = t4[(size_t)e2.z * 24 + lane];
            float f6 = t4[(size_t)e3.x * 24 + lane];
            float f7 = t4[(size_t)e3.z * 24 + lane];
            acc = fmaf(__int_as_float(e0.y), f0, acc);
            acc = fmaf(__int_as_float(e0.w), f1, acc);
            acc = fmaf(__int_as_float(e1.y), f2, acc);
            acc = fmaf(__int_as_float(e1.w), f3, acc);
            acc = fmaf(__int_as_float(e2.y), f4, acc);
            acc = fmaf(__int_as_float(e2.w), f5, acc);
            acc = fmaf(__int_as_float(e3.y), f6, acc);
            acc = fmaf(__int_as_float(e3.w), f7, acc);
        }
        if (j < endp) {
            int4 e0 = *(const int4*)(csr + j);
            int4 e1 = *(const int4*)(csr + j + 2);
            float f0 = t4[(size_t)e0.x * 24 + lane];
            float f1 = t4[(size_t)e0.z * 24 + lane];
            float f2 = t4[(size_t)e1.x * 24 + lane];
            float f3 = t4[(size_t)e1.z * 24 + lane];
            acc = fmaf(__int_as_float(e0.y), f0, acc);
            acc = fmaf(__int_as_float(e0.w), f1, acc);
            acc = fmaf(__int_as_float(e1.y), f2, acc);
            acc = fmaf(__int_as_float(e1.w), f3, acc);
        }
        float dv = dinv[v];
        acc = fmaf(dv * dv, t4[(size_t)v * 24 + lane], acc);
        val = fmaxf(acc + b4[lane], 0.f);
    }

    float m = val;
#pragma unroll
    for (int o = 16; o > 0; o >>= 1) m = fmaxf(m, __shfl_xor_sync(0xffffffffu, m, o));
    float ex = (lane < 21) ? __expf(val - m) : 0.f;
    float s = ex;
#pragma unroll
    for (int o = 16; o > 0; o >>= 1) s += __shfl_xor_sync(0xffffffffu, s, o);

    if (lane < 21) {
        out_z[(size_t)v * 21 + lane] = val;
        out_pz[(size_t)v * 21 + lane] = val - m - __logf(s);
    }
}

// ---------------------------------------------------------------------------

static inline int cdiv(long long a, int b) { return (int)((a + b - 1) / b); }

extern "C" void kernel_launch(void* const* d_in, const int* in_sizes, int n_in,
                              void* d_out, int out_size) {
    const float* x  = (const float*)d_in[0];
    const int*   ei = (const int*)d_in[1];
    const float* W1 = (const float*)d_in[2];  const float* b1 = (const float*)d_in[3];
    const float* W2 = (const float*)d_in[4];  const float* b2 = (const float*)d_in[5];
    const float* W3 = (const float*)d_in[6];  const float* b3 = (const float*)d_in[7];
    const float* W4 = (const float*)d_in[8];  const float* b4 = (const float*)d_in[9];

    const int n = in_sizes[0] / 21;
    const int E = in_sizes[1] / 2;

    float *bufA, *bufB, *dinv;
    int *ideg, *row_ptr, *scan_tmp, *bsum, *cur;
    Edge* csr;
    cudaGetSymbolAddress((void**)&bufA, g_bufA);
    cudaGetSymbolAddress((void**)&bufB, g_bufB);
    cudaGetSymbolAddress((void**)&dinv, g_dinv);
    cudaGetSymbolAddress((void**)&ideg, g_ideg);
    cudaGetSymbolAddress((void**)&row_ptr, g_rowptr);
    cudaGetSymbolAddress((void**)&scan_tmp, g_scan_tmp);
    cudaGetSymbolAddress((void**)&bsum, g_bsum);
    cudaGetSymbolAddress((void**)&cur, g_cur);
    cudaGetSymbolAddress((void**)&csr, g_csr);

    float* out_pz = (float*)d_out;
    float* out_z  = (float*)d_out + (size_t)n * 21;

    const int T = 256;
    const int nb = cdiv(n, SCAN_B);

    // --- CSR build (padded) ---
    cudaMemsetAsync(ideg, 0, (size_t)n * sizeof(int));
    k_count_deg<<<cdiv(E, T), T>>>(ei, ideg, E);
    k_scan_block<<<nb, SCAN_B>>>(ideg, scan_tmp, bsum, n, 1);
    k_scan_block<<<1, SCAN_B>>>(bsum, bsum, nullptr, nb, 0);
    k_add_off<<<nb, SCAN_B>>>(scan_tmp, bsum, ideg, row_ptr, dinv, n);
    cudaMemsetAsync(cur, 0, (size_t)n * sizeof(int));
    cudaMemsetAsync(csr, 0, sizeof(Edge) * (size_t)(E + 4 * (size_t)n));
    k_scatter<<<cdiv(E, T), T>>>(ei, row_ptr, cur, dinv, csr, E);

    const int aggGrid = cdiv((long long)n * 32, T);

    // --- layer 1: aggregate x (C=21, stride 21 -> 24), GEMM 21->168 (+bias+relu) ---
    k_agg<21, 1, 21, 24><<<aggGrid, T>>>(x, row_ptr, csr, dinv, nullptr, bufA, n);
    {
        dim3 grid(cdiv(n, GBM), cdiv(168, GBN));
        k_gemm<<<grid, T>>>(bufA, W1, b1, bufB, n, 21, 168, 24, 168, 1);   // h1: bufB s168
    }
    // --- layer 2: GEMM 168->84, fused agg+bias+relu (C=84, float4) ---
    {
        dim3 grid(cdiv(n, GBM), cdiv(84, GBN));
        k_gemm<<<grid, T>>>(bufB, W2, nullptr, bufA, n, 168, 84, 168, 84, 0); // t2: bufA s84
    }
    k_agg<84, 4, 84, 84><<<aggGrid, T>>>(bufA, row_ptr, csr, dinv, b2, bufB, n); // h2: bufB s84
    // --- layer 3: GEMM 84->42 (out stride 44), agg (C=42, float2) ---
    {
        dim3 grid(cdiv(n, GBM), cdiv(42, GBN));
        k_gemm<<<grid, T>>>(bufB, W3, nullptr, bufA, n, 84, 42, 84, 44, 0);   // t3: bufA s44
    }
    k_agg<42, 2, 44, 44><<<aggGrid, T>>>(bufA, row_ptr, csr, dinv, b3, bufB, n); // h3: bufB s44
    // --- layer 4: GEMM 42->21 (out stride 24), fused final ---
    {
        dim3 grid(cdiv(n, GBM), cdiv(21, GBN));
        k_gemm<<<grid, T>>>(bufB, W4, nullptr, bufA, n, 42, 21, 44, 24, 0);   // t4: bufA s24
    }
    k_final<<<aggGrid, T>>>(bufA, row_ptr, csr, dinv, b4, out_z, out_pz, n);
}